// round 15
// baseline (speedup 1.0000x reference)
#include <cuda_runtime.h>
#include <cuda_fp16.h>
#include <math.h>
#include <stdint.h>

// ---------------- problem constants ----------------
static const int NB   = 8;
static const int NN   = 1024;
static const int CIN  = 64;
static const int HD   = 384;
static const int NL   = 3;
static const int KNN  = 16;
static const int NHE  = 3;
static const int DHE  = 128;
static const int HD4  = 4 * HD;
static const int HB   = 4;     // batches per half-pipeline

// ---------------- device scratch (no allocs allowed) ----------------
__device__ float  g_feats [NB*NN*CIN];
__device__ float  g_h0    [NB*NN*HD];
__device__ float  g_nh    [NB*NN*HD];
__device__ float  g_sim   [NB*NN*NN];
__device__ int    g_knn   [NB*NN*KNN];
__device__ float  g_hloc  [NB*NN*HD];
__device__ float  g_o     [NB*NN*HD];
__device__ float  g_ff    [NB*NN*HD];
__device__ float  g_pool  [NB*HD];
__device__ float  g_z     [NB*HD];
__device__ float  g_bpack [3*1536];
// fp16 buffers
__device__ __half g_h16    [NB*NN*HD];
__device__ __half g_hcur16 [NB*NN*HD];
__device__ __half g_qkv16  [NB*NN*4*HD];
__device__ __half g_ao16   [NB*NN*HD];
__device__ __half g_comb16 [NB*NN*HD];
__device__ __half g_mlp116 [NB*NN*2*HD];
// fp16 weights, transposed to [N][K]
__device__ __half g_wpack16 [3*1536*384];
__device__ __half g_wr16    [2211840];
static const long long WR16_WO = 0;
static const long long WR16_W1 = 442368;
static const long long WR16_W2 = 1327104;

// ================= fp32 SIMT GEMM (exact: encoder) =========================
#define BM 128
#define BN 128
#define BKK 8
#define SPAD 132

template<bool TRANSB, bool RELU>
__global__ void __launch_bounds__(256, 2)
gemm_k(const float* __restrict__ A, const float* __restrict__ B,
       const float* __restrict__ bias, const float* __restrict__ Res,
       float* __restrict__ C,
       int M, int Nn, int K, int lda, int ldb, int ldc,
       long long sA, long long sAi, long long sB, long long sBi,
       long long sC, long long sCi, int zi, float alpha)
{
    int bz = blockIdx.z;
    int zo = bz / zi, zin = bz % zi;
    A += zo * sA + zin * sAi;
    B += zo * sB + zin * sBi;
    C += zo * sC + zin * sCi;
    if (Res) Res += zo * sC + zin * sCi;

    int m0 = blockIdx.y * BM;
    int n0 = blockIdx.x * BN;

    __shared__ float As[2][BKK][SPAD];
    __shared__ float Bs[2][BKK][SPAD];

    int tid = threadIdx.x;
    int tx = tid & 15;
    int ty = tid >> 4;

    int a_m = tid >> 1;
    int a_k = (tid & 1) * 4;
    const float* Aload = A + (long long)(m0 + a_m) * lda + a_k;

    const float* Bload;
    int b_k = 0, b_n = 0;
    if (TRANSB) {
        Bload = B + (long long)(n0 + a_m) * ldb + a_k;
    } else {
        b_k = tid >> 5;
        b_n = (tid & 31) * 4;
        Bload = B + (long long)b_k * ldb + n0 + b_n;
    }

    float4 av = *(const float4*)Aload;
    float4 bv = *(const float4*)Bload;

    As[0][a_k + 0][a_m] = av.x;
    As[0][a_k + 1][a_m] = av.y;
    As[0][a_k + 2][a_m] = av.z;
    As[0][a_k + 3][a_m] = av.w;
    if (TRANSB) {
        Bs[0][a_k + 0][a_m] = bv.x;
        Bs[0][a_k + 1][a_m] = bv.y;
        Bs[0][a_k + 2][a_m] = bv.z;
        Bs[0][a_k + 3][a_m] = bv.w;
    } else {
        *(float4*)&Bs[0][b_k][b_n] = bv;
    }
    __syncthreads();

    float acc[8][8];
    #pragma unroll
    for (int i = 0; i < 8; i++)
        #pragma unroll
        for (int j = 0; j < 8; j++) acc[i][j] = 0.f;

    int cur = 0;
    for (int k0 = 0; ; ) {
        int k1 = k0 + BKK;
        bool more = (k1 < K);
        if (more) {
            av = *(const float4*)(Aload + k1);
            if (TRANSB) bv = *(const float4*)(Bload + k1);
            else        bv = *(const float4*)(Bload + (long long)k1 * ldb);
        }

        #pragma unroll
        for (int kk = 0; kk < BKK; kk++) {
            float4 a0 = *(const float4*)&As[cur][kk][ty * 4];
            float4 a1 = *(const float4*)&As[cur][kk][64 + ty * 4];
            float4 b0 = *(const float4*)&Bs[cur][kk][tx * 4];
            float4 b1 = *(const float4*)&Bs[cur][kk][64 + tx * 4];
            float a[8] = {a0.x, a0.y, a0.z, a0.w, a1.x, a1.y, a1.z, a1.w};
            float b[8] = {b0.x, b0.y, b0.z, b0.w, b1.x, b1.y, b1.z, b1.w};
            #pragma unroll
            for (int i = 0; i < 8; i++)
                #pragma unroll
                for (int j = 0; j < 8; j++)
                    acc[i][j] = fmaf(a[i], b[j], acc[i][j]);
        }
        if (!more) break;

        int nxt = cur ^ 1;
        As[nxt][a_k + 0][a_m] = av.x;
        As[nxt][a_k + 1][a_m] = av.y;
        As[nxt][a_k + 2][a_m] = av.z;
        As[nxt][a_k + 3][a_m] = av.w;
        if (TRANSB) {
            Bs[nxt][a_k + 0][a_m] = bv.x;
            Bs[nxt][a_k + 1][a_m] = bv.y;
            Bs[nxt][a_k + 2][a_m] = bv.z;
            Bs[nxt][a_k + 3][a_m] = bv.w;
        } else {
            *(float4*)&Bs[nxt][b_k][b_n] = bv;
        }
        __syncthreads();
        cur = nxt;
        k0 = k1;
    }

    #pragma unroll
    for (int ih = 0; ih < 2; ih++) {
        #pragma unroll
        for (int i = 0; i < 4; i++) {
            int m = m0 + ih * 64 + ty * 4 + i;
            #pragma unroll
            for (int jh = 0; jh < 2; jh++) {
                int n = n0 + jh * 64 + tx * 4;
                float4 r;
                r.x = acc[ih * 4 + i][jh * 4 + 0] * alpha;
                r.y = acc[ih * 4 + i][jh * 4 + 1] * alpha;
                r.z = acc[ih * 4 + i][jh * 4 + 2] * alpha;
                r.w = acc[ih * 4 + i][jh * 4 + 3] * alpha;
                if (bias) {
                    float4 bb = *(const float4*)(bias + n);
                    r.x += bb.x; r.y += bb.y; r.z += bb.z; r.w += bb.w;
                }
                if (Res) {
                    float4 rr = *(const float4*)(Res + (long long)m * ldc + n);
                    r.x += rr.x; r.y += rr.y; r.z += rr.z; r.w += rr.w;
                }
                if (RELU) {
                    r.x = fmaxf(r.x, 0.f); r.y = fmaxf(r.y, 0.f);
                    r.z = fmaxf(r.z, 0.f); r.w = fmaxf(r.w, 0.f);
                }
                *(float4*)(C + (long long)m * ldc + n) = r;
            }
        }
    }
}

// ================= symmetric cosine-sim GEMM (fp32 exact) ==================
__global__ void __launch_bounds__(256, 2)
sim_gemm_k(const float* __restrict__ nh, float* __restrict__ sim)
{
    int t = blockIdx.x;
    int bi = 0;
    while ((bi + 1) * (bi + 2) / 2 <= t) bi++;
    int bj = t - bi * (bi + 1) / 2;
    int z = blockIdx.z;

    const float* A = nh + (long long)z * NN * HD;
    float* C = sim + (long long)z * NN * NN;
    int m0 = bi * 128;
    int n0 = bj * 128;

    __shared__ float As[2][BKK][SPAD];
    __shared__ float Bs[2][BKK][SPAD];

    int tid = threadIdx.x;
    int tx = tid & 15;
    int ty = tid >> 4;

    int a_m = tid >> 1;
    int a_k = (tid & 1) * 4;
    const float* Aload = A + (long long)(m0 + a_m) * HD + a_k;
    const float* Bload = A + (long long)(n0 + a_m) * HD + a_k;

    float4 av = *(const float4*)Aload;
    float4 bv = *(const float4*)Bload;

    As[0][a_k + 0][a_m] = av.x;
    As[0][a_k + 1][a_m] = av.y;
    As[0][a_k + 2][a_m] = av.z;
    As[0][a_k + 3][a_m] = av.w;
    Bs[0][a_k + 0][a_m] = bv.x;
    Bs[0][a_k + 1][a_m] = bv.y;
    Bs[0][a_k + 2][a_m] = bv.z;
    Bs[0][a_k + 3][a_m] = bv.w;
    __syncthreads();

    float acc[8][8];
    #pragma unroll
    for (int i = 0; i < 8; i++)
        #pragma unroll
        for (int j = 0; j < 8; j++) acc[i][j] = 0.f;

    int cur = 0;
    for (int k0 = 0; ; ) {
        int k1 = k0 + BKK;
        bool more = (k1 < HD);
        if (more) {
            av = *(const float4*)(Aload + k1);
            bv = *(const float4*)(Bload + k1);
        }
        #pragma unroll
        for (int kk = 0; kk < BKK; kk++) {
            float4 a0 = *(const float4*)&As[cur][kk][ty * 4];
            float4 a1 = *(const float4*)&As[cur][kk][64 + ty * 4];
            float4 b0 = *(const float4*)&Bs[cur][kk][tx * 4];
            float4 b1 = *(const float4*)&Bs[cur][kk][64 + tx * 4];
            float a[8] = {a0.x, a0.y, a0.z, a0.w, a1.x, a1.y, a1.z, a1.w};
            float b[8] = {b0.x, b0.y, b0.z, b0.w, b1.x, b1.y, b1.z, b1.w};
            #pragma unroll
            for (int i = 0; i < 8; i++)
                #pragma unroll
                for (int j = 0; j < 8; j++)
                    acc[i][j] = fmaf(a[i], b[j], acc[i][j]);
        }
        if (!more) break;

        int nxt = cur ^ 1;
        As[nxt][a_k + 0][a_m] = av.x;
        As[nxt][a_k + 1][a_m] = av.y;
        As[nxt][a_k + 2][a_m] = av.z;
        As[nxt][a_k + 3][a_m] = av.w;
        Bs[nxt][a_k + 0][a_m] = bv.x;
        Bs[nxt][a_k + 1][a_m] = bv.y;
        Bs[nxt][a_k + 2][a_m] = bv.z;
        Bs[nxt][a_k + 3][a_m] = bv.w;
        __syncthreads();
        cur = nxt;
        k0 = k1;
    }

    bool mirror = (bi != bj);
    #pragma unroll
    for (int ih = 0; ih < 2; ih++) {
        #pragma unroll
        for (int i = 0; i < 4; i++) {
            int m = m0 + ih * 64 + ty * 4 + i;
            #pragma unroll
            for (int jh = 0; jh < 2; jh++) {
                int n = n0 + jh * 64 + tx * 4;
                float4 r;
                r.x = acc[ih * 4 + i][jh * 4 + 0];
                r.y = acc[ih * 4 + i][jh * 4 + 1];
                r.z = acc[ih * 4 + i][jh * 4 + 2];
                r.w = acc[ih * 4 + i][jh * 4 + 3];
                *(float4*)(C + (long long)m * NN + n) = r;
                if (mirror) {
                    C[(long long)(n + 0) * NN + m] = r.x;
                    C[(long long)(n + 1) * NN + m] = r.y;
                    C[(long long)(n + 2) * NN + m] = r.z;
                    C[(long long)(n + 3) * NN + m] = r.w;
                }
            }
        }
    }
}

// ================= async + mma + ldmatrix helpers =========================
__device__ __forceinline__ void cpa16(void* dst, const void* src)
{
    uint32_t s = (uint32_t)__cvta_generic_to_shared(dst);
    asm volatile("cp.async.cg.shared.global [%0], [%1], 16;" :: "r"(s), "l"(src));
}
template<int N> __device__ __forceinline__ void cpa_wait()
{
    asm volatile("cp.async.wait_group %0;" :: "n"(N));
}
__device__ __forceinline__ void cpa_commit()
{
    asm volatile("cp.async.commit_group;");
}
__device__ __forceinline__ void mma_f16(float* d, const uint32_t* a, uint32_t b0, uint32_t b1)
{
    asm volatile(
        "mma.sync.aligned.m16n8k16.row.col.f32.f16.f16.f32 "
        "{%0,%1,%2,%3}, {%4,%5,%6,%7}, {%8,%9}, {%0,%1,%2,%3};"
        : "+f"(d[0]), "+f"(d[1]), "+f"(d[2]), "+f"(d[3])
        : "r"(a[0]), "r"(a[1]), "r"(a[2]), "r"(a[3]), "r"(b0), "r"(b1));
}
__device__ __forceinline__ void ldsm4(uint32_t* r, const void* smem)
{
    uint32_t a = (uint32_t)__cvta_generic_to_shared(smem);
    asm volatile("ldmatrix.sync.aligned.m8n8.x4.shared.b16 {%0,%1,%2,%3}, [%4];"
        : "=r"(r[0]), "=r"(r[1]), "=r"(r[2]), "=r"(r[3]) : "r"(a));
}
__device__ __forceinline__ void ldsm4t(uint32_t* r, const void* smem)
{
    uint32_t a = (uint32_t)__cvta_generic_to_shared(smem);
    asm volatile("ldmatrix.sync.aligned.m8n8.x4.trans.shared.b16 {%0,%1,%2,%3}, [%4];"
        : "=r"(r[0]), "=r"(r[1]), "=r"(r[2]), "=r"(r[3]) : "r"(a));
}

// ================= fp16 tensor-core GEMM ===================================
#define HRS 40

template<bool RELU, int OUTMODE, bool HASRES, int NTILE>
__global__ void __launch_bounds__(256, 2)
h16gemm_k(const __half* __restrict__ A, const __half* __restrict__ B,
          const float* __restrict__ bias, const __half* __restrict__ Res,
          void* __restrict__ Cv,
          int K, int lda, int ldb, int ldc,
          long long sA, long long sC)
{
    constexpr int NT  = NTILE / 16;
    constexpr int ASZ = 128 * HRS;
    constexpr int BSZ = NTILE * HRS;

    extern __shared__ __align__(16) __half hsm[];
    __half* As = hsm;
    __half* Bs = hsm + 3 * ASZ;

    int z = blockIdx.z;
    A += (long long)z * sA;
    long long coff = (long long)z * sC;

    int m0 = blockIdx.y * 128;
    int n0 = blockIdx.x * NTILE;

    int tid = threadIdx.x;
    int lane = tid & 31, wid = tid >> 5;
    int wm = (wid & 3) * 32;
    int wn = (wid >> 2) * (NTILE / 2);
    int tig = lane & 3, grp = lane >> 2;
    int lr = lane & 7, ls = lane >> 3;   // ldmatrix row / tile-select

    int ar0 = tid >> 2,          as0 = (tid & 3) * 8;
    int ar1 = (tid + 256) >> 2,  as1 = ((tid + 256) & 3) * 8;
    const __half* Ag0 = A + (long long)(m0 + ar0) * lda + as0;
    const __half* Ag1 = A + (long long)(m0 + ar1) * lda + as1;
    int ao0 = ar0 * HRS + as0;
    int ao1 = ar1 * HRS + as1;

    int br0 = tid >> 2, bs0 = (tid & 3) * 8;
    const __half* Bg0 = B + (long long)(n0 + br0) * ldb + bs0;
    int bo0 = br0 * HRS + bs0;
    const __half* Bg1 = nullptr; int bo1 = 0;
    if (NTILE == 128) {
        int br1 = (tid + 256) >> 2, bs1 = ((tid + 256) & 3) * 8;
        Bg1 = B + (long long)(n0 + br1) * ldb + bs1;
        bo1 = br1 * HRS + bs1;
    }

    const int kIt = K >> 5;

    cpa16(&As[ao0], Ag0);
    cpa16(&As[ao1], Ag1);
    cpa16(&Bs[bo0], Bg0);
    if (NTILE == 128) cpa16(&Bs[bo1], Bg1);
    cpa_commit();
    cpa16(&As[ASZ + ao0], Ag0 + 32);
    cpa16(&As[ASZ + ao1], Ag1 + 32);
    cpa16(&Bs[BSZ + bo0], Bg0 + 32);
    if (NTILE == 128) cpa16(&Bs[BSZ + bo1], Bg1 + 32);
    cpa_commit();

    float acc[2][NT][4];
    #pragma unroll
    for (int mt = 0; mt < 2; mt++)
        #pragma unroll
        for (int nt = 0; nt < NT; nt++)
            #pragma unroll
            for (int r = 0; r < 4; r++) acc[mt][nt][r] = 0.f;

    int bufm = 0;
    for (int it = 0; it < kIt; it++) {
        if (it + 1 < kIt) cpa_wait<1>(); else cpa_wait<0>();
        __syncthreads();

        if (it + 2 < kIt) {
            int pb = bufm + 2; if (pb >= 3) pb -= 3;
            int kf = (it + 2) << 5;
            cpa16(&As[pb * ASZ + ao0], Ag0 + kf);
            cpa16(&As[pb * ASZ + ao1], Ag1 + kf);
            cpa16(&Bs[pb * BSZ + bo0], Bg0 + kf);
            if (NTILE == 128) cpa16(&Bs[pb * BSZ + bo1], Bg1 + kf);
            cpa_commit();
        }

        const __half* Ac = As + bufm * ASZ;
        const __half* Bc = Bs + bufm * BSZ;
        #pragma unroll
        for (int ksi = 0; ksi < 2; ksi++) {
            int kc = ksi * 16;
            uint32_t af[2][4], bf[NT][2];
            #pragma unroll
            for (int mt = 0; mt < 2; mt++) {
                // tiles: (m lo,k lo),(m hi,k lo),(m lo,k hi),(m hi,k hi)
                int row = wm + mt * 16 + (ls & 1) * 8 + lr;
                int col = kc + (ls >> 1) * 8;
                ldsm4(af[mt], &Ac[row * HRS + col]);
            }
            #pragma unroll
            for (int np = 0; np < NT / 2; np++) {
                // tiles: (n0,k lo),(n0,k hi),(n1,k lo),(n1,k hi)
                int row = wn + (2 * np + (ls >> 1)) * 8 + lr;
                int col = kc + (ls & 1) * 8;
                uint32_t q[4];
                ldsm4(q, &Bc[row * HRS + col]);
                bf[2 * np][0] = q[0]; bf[2 * np][1] = q[1];
                bf[2 * np + 1][0] = q[2]; bf[2 * np + 1][1] = q[3];
            }
            #pragma unroll
            for (int mt = 0; mt < 2; mt++)
                #pragma unroll
                for (int nt = 0; nt < NT; nt++)
                    mma_f16(acc[mt][nt], af[mt], bf[nt][0], bf[nt][1]);
        }
        bufm++; if (bufm >= 3) bufm = 0;
    }

    #pragma unroll
    for (int mt = 0; mt < 2; mt++) {
        #pragma unroll
        for (int hf = 0; hf < 2; hf++) {
            int m = m0 + wm + mt * 16 + grp + hf * 8;
            #pragma unroll
            for (int nt = 0; nt < NT; nt++) {
                int n = n0 + wn + nt * 8 + 2 * tig;
                float rx = acc[mt][nt][hf * 2 + 0] + bias[n];
                float ry = acc[mt][nt][hf * 2 + 1] + bias[n + 1];
                if (HASRES) {
                    __half2 rr = *(const __half2*)&Res[coff + (long long)m * ldc + n];
                    float2 rf = __half22float2(rr);
                    rx += rf.x; ry += rf.y;
                }
                if (RELU) { rx = fmaxf(rx, 0.f); ry = fmaxf(ry, 0.f); }
                if (OUTMODE == 2) {
                    *(__half2*)((__half*)Cv + coff + (long long)m * ldc + n) =
                        __floats2half2_rn(rx, ry);
                } else {
                    float2 r2; r2.x = rx; r2.y = ry;
                    *(float2*)((float*)Cv + coff + (long long)m * ldc + n) = r2;
                }
            }
        }
    }
}

// ================= fp16 flash attention (ldmatrix + m16n8k16) ==============
#define QH 136
#define KH 136
#define VH 136
#define PH 40
static const int FLASH16_SMEM = (128*QH + 2*32*KH + 2*32*VH + 128*PH) * 2;

__global__ void __launch_bounds__(256, 2)
flash16_kernel(const __half* __restrict__ qkv, __half* __restrict__ ao)
{
    extern __shared__ __align__(16) __half fsm[];
    __half* Qs = fsm;
    __half* Ks = Qs + 128 * QH;
    __half* Vs = Ks + 2 * 32 * KH;
    __half* Ps = Vs + 2 * 32 * VH;

    int qt = blockIdx.x;
    int bh = blockIdx.y;
    int b = bh / NHE, h = bh - b * NHE;
    const __half* qbase = qkv + (long long)b * NN * HD4 + (long long)qt * 128 * HD4 + HD + h * DHE;
    const __half* kbase = qkv + (long long)b * NN * HD4 + 2 * HD + h * DHE;
    const __half* vbase = qkv + (long long)b * NN * HD4 + 3 * HD + h * DHE;

    int tid = threadIdx.x;
    int lane = tid & 31, wid = tid >> 5;
    int tig = lane & 3, grp = lane >> 2;
    int lr = lane & 7, ls = lane >> 3;
    int wq = wid * 16;

    #pragma unroll
    for (int c = 0; c < 8; c++) {
        int chunk = tid + c * 256;
        int row = chunk >> 4, col = (chunk & 15) * 8;
        cpa16(&Qs[row * QH + col], qbase + (long long)row * HD4 + col);
    }
    #pragma unroll
    for (int c = 0; c < 2; c++) {
        int chunk = tid + c * 256;
        int row = chunk >> 4, col = (chunk & 15) * 8;
        cpa16(&Ks[row * KH + col], kbase + (long long)row * HD4 + col);
        cpa16(&Vs[row * VH + col], vbase + (long long)row * HD4 + col);
    }
    cpa_commit();

    float Oacc[16][4];
    #pragma unroll
    for (int nt = 0; nt < 16; nt++)
        #pragma unroll
        for (int j = 0; j < 4; j++) Oacc[nt][j] = 0.f;
    float m0r = -1e30f, m1r = -1e30f;
    float l0 = 0.f, l1 = 0.f;
    const float alpha = 0.08838834764831843f;

    int cur = 0;
    for (int it = 0; it < 32; it++) {
        bool more = (it + 1 < 32);
        if (more) {
            int nxt = cur ^ 1;
            const __half* kb = kbase + (long long)(it + 1) * 32 * HD4;
            const __half* vb = vbase + (long long)(it + 1) * 32 * HD4;
            #pragma unroll
            for (int c = 0; c < 2; c++) {
                int chunk = tid + c * 256;
                int row = chunk >> 4, col = (chunk & 15) * 8;
                cpa16(&Ks[nxt * 32 * KH + row * KH + col], kb + (long long)row * HD4 + col);
                cpa16(&Vs[nxt * 32 * VH + row * VH + col], vb + (long long)row * HD4 + col);
            }
            cpa_commit();
            cpa_wait<1>();
        } else {
            cpa_wait<0>();
        }
        __syncthreads();

        const __half* Kc = Ks + cur * 32 * KH;
        const __half* Vc = Vs + cur * 32 * VH;

        // S = Q @ K^T
        float s[4][4];
        #pragma unroll
        for (int nt = 0; nt < 4; nt++)
            #pragma unroll
            for (int j = 0; j < 4; j++) s[nt][j] = 0.f;
        #pragma unroll
        for (int ks = 0; ks < 8; ks++) {
            int kc = ks * 16;
            uint32_t af[4];
            {
                int row = wq + (ls & 1) * 8 + lr;
                int col = kc + (ls >> 1) * 8;
                ldsm4(af, &Qs[row * QH + col]);
            }
            uint32_t bf[4][2];
            #pragma unroll
            for (int np = 0; np < 2; np++) {
                int row = (2 * np + (ls >> 1)) * 8 + lr;
                int col = kc + (ls & 1) * 8;
                uint32_t q[4];
                ldsm4(q, &Kc[row * KH + col]);
                bf[2 * np][0] = q[0]; bf[2 * np][1] = q[1];
                bf[2 * np + 1][0] = q[2]; bf[2 * np + 1][1] = q[3];
            }
            #pragma unroll
            for (int nt = 0; nt < 4; nt++)
                mma_f16(s[nt], af, bf[nt][0], bf[nt][1]);
        }

        // online softmax (fp32 exact)
        float t0 = -1e30f, t1 = -1e30f;
        #pragma unroll
        for (int nt = 0; nt < 4; nt++) {
            s[nt][0] *= alpha; s[nt][1] *= alpha;
            s[nt][2] *= alpha; s[nt][3] *= alpha;
            t0 = fmaxf(t0, fmaxf(s[nt][0], s[nt][1]));
            t1 = fmaxf(t1, fmaxf(s[nt][2], s[nt][3]));
        }
        t0 = fmaxf(t0, __shfl_xor_sync(0xffffffffu, t0, 1));
        t0 = fmaxf(t0, __shfl_xor_sync(0xffffffffu, t0, 2));
        t1 = fmaxf(t1, __shfl_xor_sync(0xffffffffu, t1, 1));
        t1 = fmaxf(t1, __shfl_xor_sync(0xffffffffu, t1, 2));
        float mn0 = fmaxf(m0r, t0), mn1 = fmaxf(m1r, t1);
        float f0 = __expf(m0r - mn0), f1 = __expf(m1r - mn1);
        float ps0 = 0.f, ps1 = 0.f;
        #pragma unroll
        for (int nt = 0; nt < 4; nt++) {
            float p0 = __expf(s[nt][0] - mn0);
            float p1 = __expf(s[nt][1] - mn0);
            float p2 = __expf(s[nt][2] - mn1);
            float p3 = __expf(s[nt][3] - mn1);
            ps0 += p0 + p1;
            ps1 += p2 + p3;
            *(__half2*)&Ps[(wq + grp) * PH + nt * 8 + 2 * tig] = __floats2half2_rn(p0, p1);
            *(__half2*)&Ps[(wq + grp + 8) * PH + nt * 8 + 2 * tig] = __floats2half2_rn(p2, p3);
        }
        ps0 += __shfl_xor_sync(0xffffffffu, ps0, 1);
        ps0 += __shfl_xor_sync(0xffffffffu, ps0, 2);
        ps1 += __shfl_xor_sync(0xffffffffu, ps1, 1);
        ps1 += __shfl_xor_sync(0xffffffffu, ps1, 2);
        l0 = l0 * f0 + ps0;
        l1 = l1 * f1 + ps1;
        m0r = mn0; m1r = mn1;
        #pragma unroll
        for (int nt = 0; nt < 16; nt++) {
            Oacc[nt][0] *= f0; Oacc[nt][1] *= f0;
            Oacc[nt][2] *= f1; Oacc[nt][3] *= f1;
        }
        __syncwarp();

        // O += P @ V  (V^T fragments via ldmatrix.trans)
        #pragma unroll
        for (int ks = 0; ks < 2; ks++) {
            int kc = ks * 16;
            uint32_t af[4];
            {
                int row = wq + (ls & 1) * 8 + lr;
                int col = kc + (ls >> 1) * 8;
                ldsm4(af, &Ps[row * PH + col]);
            }
            #pragma unroll
            for (int np = 0; np < 8; np++) {
                // trans tiles: (n=2np, k lo),(2np, k hi),(2np+1, k lo),(2np+1, k hi)
                int ntp = 2 * np + (ls >> 1);
                int koff = (ls & 1) * 8;
                uint32_t q[4];
                ldsm4t(q, &Vc[(kc + koff + lr) * VH + ntp * 8]);
                mma_f16(Oacc[2 * np], af, q[0], q[1]);
                mma_f16(Oacc[2 * np + 1], af, q[2], q[3]);
            }
        }
        if (!more) break;
        __syncthreads();
        cur ^= 1;
    }

    float inv0 = 1.f / l0, inv1 = 1.f / l1;
    int r0 = qt * 128 + wq + grp;
    __half* o0 = ao + ((long long)b * NN + r0) * HD + h * DHE;
    __half* o1 = o0 + 8 * HD;
    #pragma unroll
    for (int nt = 0; nt < 16; nt++) {
        int col = nt * 8 + 2 * tig;
        *(__half2*)(o0 + col) = __floats2half2_rn(Oacc[nt][0] * inv0, Oacc[nt][1] * inv0);
        *(__half2*)(o1 + col) = __floats2half2_rn(Oacc[nt][2] * inv1, Oacc[nt][3] * inv1);
    }
}

// ---------------- small kernels ----------------
__global__ void feats_kernel(const float* __restrict__ x, float* __restrict__ feats)
{
    long long i = (long long)blockIdx.x * blockDim.x + threadIdx.x;
    if (i >= (long long)NB * NN * CIN) return;
    int c = (int)(i & (CIN - 1));
    long long bn = i >> 6;
    int n = (int)(bn & (NN - 1));
    int b = (int)(bn >> 10);
    feats[i] = x[((long long)b * CIN + c) * NN + n];
}

__global__ void prep16_kernel(const float* __restrict__ gcn_W, const float* __restrict__ Wq,
                              const float* __restrict__ Wk, const float* __restrict__ Wv,
                              const float* __restrict__ gcn_b, const float* __restrict__ bq,
                              const float* __restrict__ bk, const float* __restrict__ bv,
                              const float* __restrict__ Wo, const float* __restrict__ W1,
                              const float* __restrict__ W2,
                              __half* __restrict__ wpack, float* __restrict__ bpack,
                              __half* __restrict__ wr)
{
    int i = blockIdx.x * blockDim.x + threadIdx.x;
    const int NWP = 3 * 1536 * 384;
    const int NBP = 3 * 1536;
    const int NWO = 3 * 384 * 384;
    const int NW1 = 3 * 768 * 384;
    if (i < NWP) {
        int l = i / (1536 * 384);
        int rem = i - l * (1536 * 384);
        int n = rem / 384;
        int k = rem - n * 384;
        int s2 = n / 384;
        int cc = n - s2 * 384;
        const float* src = (s2 == 0) ? gcn_W : (s2 == 1) ? Wq : (s2 == 2) ? Wk : Wv;
        wpack[i] = __float2half(src[((long long)l * 384 + k) * 384 + cc]);
        return;
    }
    int j = i - NWP;
    if (j < NBP) {
        int l = j / 1536;
        int c = j - l * 1536;
        int s2 = c / 384, cc = c - s2 * 384;
        const float* src = (s2 == 0) ? gcn_b : (s2 == 1) ? bq : (s2 == 2) ? bk : bv;
        bpack[j] = src[l * 384 + cc];
        return;
    }
    j -= NBP;
    if (j < NWO) {
        int l = j / (384 * 384);
        int rem = j - l * (384 * 384);
        int n = rem / 384, k = rem - n * 384;
        wr[WR16_WO + j] = __float2half(Wo[((long long)l * 384 + k) * 384 + n]);
        return;
    }
    j -= NWO;
    if (j < NW1) {
        int l = j / (768 * 384);
        int rem = j - l * (768 * 384);
        int n = rem / 384, k = rem - n * 384;
        wr[WR16_W1 + j] = __float2half(W1[((long long)l * 384 + k) * 768 + n]);
        return;
    }
    j -= NW1;
    if (j < NW1) {
        int l = j / (384 * 768);
        int rem = j - l * (384 * 768);
        int n = rem / 768, k = rem - n * 768;
        wr[WR16_W2 + j] = __float2half(W2[((long long)l * 768 + k) * 384 + n]);
        return;
    }
}

__device__ __forceinline__ void block_reduce2(float& s1, float& s2)
{
    __shared__ float b1[4], b2[4];
    #pragma unroll
    for (int o = 16; o > 0; o >>= 1) {
        s1 += __shfl_down_sync(0xffffffffu, s1, o);
        s2 += __shfl_down_sync(0xffffffffu, s2, o);
    }
    int w = threadIdx.x >> 5;
    if ((threadIdx.x & 31) == 0) { b1[w] = s1; b2[w] = s2; }
    __syncthreads();
    s1 = b1[0] + b1[1] + b1[2] + b1[3];
    s2 = b2[0] + b2[1] + b2[2] + b2[3];
}

__global__ void norm_kernel(const float* __restrict__ h0, float* __restrict__ nh,
                            __half* __restrict__ h16)
{
    long long bn = blockIdx.x;
    int t = threadIdx.x; // 128
    const float* r = h0 + bn * HD;
    float v0 = r[t], v1 = r[t + 128], v2 = r[t + 256];
    float ss = v0 * v0 + v1 * v1 + v2 * v2, dummy = 0.f;
    block_reduce2(ss, dummy);
    float rinv = rsqrtf(ss);
    float* o = nh + bn * HD;
    o[t] = v0 * rinv; o[t + 128] = v1 * rinv; o[t + 256] = v2 * rinv;
    __half* o2 = h16 + bn * HD;
    o2[t] = __float2half(v0);
    o2[t + 128] = __float2half(v1);
    o2[t + 256] = __float2half(v2);
}

__global__ void topk_warp_kernel(const float* __restrict__ sim, int* __restrict__ knn)
{
    int warp = blockIdx.x * (blockDim.x >> 5) + (threadIdx.x >> 5);
    int lane = threadIdx.x & 31;
    int n = warp & (NN - 1);
    const float* row = sim + (long long)warp * NN;
    float v[32];
    #pragma unroll
    for (int j = 0; j < 32; j++) {
        int m = j * 32 + lane;
        v[j] = (m == n) ? -3e38f : row[m];
    }
    unsigned taken = 0;
    int* o = knn + (long long)warp * KNN;
    for (int r = 0; r < KNN; r++) {
        float bv = -3e38f; int bj = 0;
        #pragma unroll
        for (int j = 0; j < 32; j++) {
            bool free_ = !((taken >> j) & 1u);
            if (free_ && v[j] > bv) { bv = v[j]; bj = j; }
        }
        int bidx = bj * 32 + lane;
        #pragma unroll
        for (int off = 16; off > 0; off >>= 1) {
            float ov = __shfl_xor_sync(0xffffffffu, bv, off);
            int   oi = __shfl_xor_sync(0xffffffffu, bidx, off);
            if (ov > bv || (ov == bv && oi < bidx)) { bv = ov; bidx = oi; }
        }
        if ((bidx & 31) == lane) taken |= 1u << (bidx >> 5);
        if (lane == 0) o[r] = bidx;
    }
}

__global__ void gcn_agg_ln(const __half* __restrict__ hcur, const __half* __restrict__ xw,
                           int ldx,
                           const int* __restrict__ knn,
                           const float* __restrict__ scale, const float* __restrict__ bias,
                           float* __restrict__ out)
{
    int bn = blockIdx.x;
    int b = bn >> 10;
    int t = threadIdx.x; // 128
    __shared__ int sidx[KNN];
    if (t < KNN) sidx[t] = knn[(long long)bn * KNN + t];
    __syncthreads();
    const __half* xr = xw + (long long)bn * ldx;
    float a0 = __half2float(xr[t]);
    float a1 = __half2float(xr[t + 128]);
    float a2 = __half2float(xr[t + 256]);
    #pragma unroll 4
    for (int j = 0; j < KNN; j++) {
        const __half* r = xw + ((long long)(b * NN) + sidx[j]) * ldx;
        a0 += __half2float(r[t]);
        a1 += __half2float(r[t + 128]);
        a2 += __half2float(r[t + 256]);
    }
    const __half* h = hcur + (long long)bn * HD;
    const float inv17 = 1.f / 17.f;
    float v0 = __half2float(h[t]) + a0 * inv17;
    float v1 = __half2float(h[t + 128]) + a1 * inv17;
    float v2 = __half2float(h[t + 256]) + a2 * inv17;
    float s1 = v0 + v1 + v2;
    float s2 = v0 * v0 + v1 * v1 + v2 * v2;
    block_reduce2(s1, s2);
    float mu = s1 * (1.f / HD);
    float var = s2 * (1.f / HD) - mu * mu;
    float rstd = rsqrtf(var + 1e-5f);
    float* o = out + (long long)bn * HD;
    o[t]       = (v0 - mu) * rstd * scale[t]       + bias[t];
    o[t + 128] = (v1 - mu) * rstd * scale[t + 128] + bias[t + 128];
    o[t + 256] = (v2 - mu) * rstd * scale[t + 256] + bias[t + 256];
}

template<bool AHALF>
__global__ void add_ln_h(const void* __restrict__ av, const float* __restrict__ b,
                         const float* __restrict__ plus,
                         const float* __restrict__ scale, const float* __restrict__ bias,
                         __half* __restrict__ out)
{
    long long bn = blockIdx.x;
    int t = threadIdx.x; // 128
    float v0, v1, v2;
    if (AHALF) {
        const __half* ar = (const __half*)av + bn * HD;
        v0 = __half2float(ar[t]);
        v1 = __half2float(ar[t + 128]);
        v2 = __half2float(ar[t + 256]);
    } else {
        const float* ar = (const float*)av + bn * HD;
        v0 = ar[t]; v1 = ar[t + 128]; v2 = ar[t + 256];
    }
    if (b) {
        const float* br = b + bn * HD;
        v0 += br[t]; v1 += br[t + 128]; v2 += br[t + 256];
    }
    float s1 = v0 + v1 + v2;
    float s2 = v0 * v0 + v1 * v1 + v2 * v2;
    block_reduce2(s1, s2);
    float mu = s1 * (1.f / HD);
    float var = s2 * (1.f / HD) - mu * mu;
    float rstd = rsqrtf(var + 1e-5f);
    float y0 = (v0 - mu) * rstd * scale[t]       + bias[t];
    float y1 = (v1 - mu) * rstd * scale[t + 128] + bias[t + 128];
    float y2 = (v2 - mu) * rstd * scale[t + 256] + bias[t + 256];
    if (plus) {
        const float* pr = plus + bn * HD;
        y0 += pr[t]; y1 += pr[t + 128]; y2 += pr[t + 256];
    }
    __half* o = out + bn * HD;
    o[t]       = __float2half(y0);
    o[t + 128] = __float2half(y1);
    o[t + 256] = __float2half(y2);
}

__global__ void pool_kernel(const __half* __restrict__ h, float* __restrict__ pooled)
{
    int b = blockIdx.x;
    int t = threadIdx.x; // 384
    float s = 0.f;
    const __half* base = h + (long long)b * NN * HD + t;
    for (int n = 0; n < NN; n++) s += __half2float(base[(long long)n * HD]);
    pooled[b * HD + t] = s * (1.f / NN);
}

__global__ void fin1_kernel(const float* __restrict__ pooled, const float* __restrict__ W,
                            const float* __restrict__ bias, float* __restrict__ z)
{
    int b = blockIdx.x;
    int j = threadIdx.x; // 384
    const float* p = pooled + b * HD;
    float s = bias[j];
    for (int k = 0; k < HD; k++) s = fmaf(p[k], W[k * HD + j], s);
    z[b * HD + j] = fmaxf(s, 0.f);
}

__global__ void fin2_kernel(const float* __restrict__ z, const float* __restrict__ W,
                            const float* __restrict__ bias, float* __restrict__ out)
{
    int b = blockIdx.x;
    int j = threadIdx.x; // 128
    const float* p = z + b * HD;
    float s = bias[j];
    for (int k = 0; k < HD; k++) s = fmaf(p[k], W[k * 128 + j], s);
    out[b * 128 + j] = s;
}

// ---------------- host helpers ----------------
static void gemm_f32(const float* A, const float* B, const float* bias, const float* Res, float* C,
                     int M, int Nn, int K, int lda, int ldb, int ldc,
                     long long sA, long long sAi, long long sB, long long sBi,
                     long long sC, long long sCi, int zi, int nz,
                     float alpha, bool transb, bool relu, cudaStream_t st = 0)
{
    dim3 grid(Nn / BN, M / BM, nz), block(256);
    if (transb) {
        if (relu) gemm_k<true, true ><<<grid, block, 0, st>>>(A, B, bias, Res, C, M, Nn, K, lda, ldb, ldc, sA, sAi, sB, sBi, sC, sCi, zi, alpha);
        else      gemm_k<true, false><<<grid, block, 0, st>>>(A, B, bias, Res, C, M, Nn, K, lda, ldb, ldc, sA, sAi, sB, sBi, sC, sCi, zi, alpha);
    } else {
        if (relu) gemm_k<false, true ><<<grid, block, 0, st>>>(A, B, bias, Res, C, M, Nn, K, lda, ldb, ldc, sA, sAi, sB, sBi, sC, sCi, zi, alpha);
        else      gemm_k<false, false><<<grid, block, 0, st>>>(A, B, bias, Res, C, M, Nn, K, lda, ldb, ldc, sA, sAi, sB, sBi, sC, sCi, zi, alpha);
    }
}

template<typename T> static T* sym_addr(const void* sym)
{
    void* p = nullptr;
    cudaGetSymbolAddress(&p, sym);
    return (T*)p;
}

extern "C" void kernel_launch(void* const* d_in, const int* in_sizes, int n_in,
                              void* d_out, int out_size)
{
    const float* x      = (const float*)d_in[0];
    const float* W_enc  = (const float*)d_in[1];
    const float* b_enc  = (const float*)d_in[2];
    const float* gcn_W  = (const float*)d_in[3];
    const float* gcn_b  = (const float*)d_in[4];
    const float* Wq     = (const float*)d_in[5];
    const float* bq     = (const float*)d_in[6];
    const float* Wk     = (const float*)d_in[7];
    const float* bk     = (const float*)d_in[8];
    const float* Wv     = (const float*)d_in[9];
    const float* bv     = (const float*)d_in[10];
    const float* Wo     = (const float*)d_in[11];
    const float* bo     = (const float*)d_in[12];
    const float* lnsc   = (const float*)d_in[13];
    const float* lnbi   = (const float*)d_in[14];
    const float* W1     = (const float*)d_in[15];
    const float* b1     = (const float*)d_in[16];
    const float* W2     = (const float*)d_in[17];
    const float* b2     = (const float*)d_in[18];
    const float* lin1_W = (const float*)d_in[19];
    const float* lin1_b = (const float*)d_in[20];
    const float* lin2_W = (const float*)d_in[21];
    const float* lin2_b = (const float*)d_in[22];
    float* outp = (float*)d_out;

    float*  featsp  = sym_addr<float>(g_feats);
    float*  h0p     = sym_addr<float>(g_h0);
    float*  nhp     = sym_addr<float>(g_nh);
    float*  simp    = sym_addr<float>(g_sim);
    int*    knnp    = sym_addr<int>(g_knn);
    float*  hlocp   = sym_addr<float>(g_hloc);
    float*  op      = sym_addr<float>(g_o);
    float*  ffp     = sym_addr<float>(g_ff);
    float*  poolp   = sym_addr<float>(g_pool);
    float*  zp      = sym_addr<float>(g_z);
    float*  bpackp  = sym_addr<float>(g_bpack);
    __half* h16p    = sym_addr<__half>(g_h16);
    __half* hcur16p = sym_addr<__half>(g_hcur16);
    __half* qkv16p  = sym_addr<__half>(g_qkv16);
    __half* ao16p   = sym_addr<__half>(g_ao16);
    __half* comb16p = sym_addr<__half>(g_comb16);
    __half* mlp116p = sym_addr<__half>(g_mlp116);
    __half* wpack16p= sym_addr<__half>(g_wpack16);
    __half* wr16p   = sym_addr<__half>(g_wr16);

    cudaFuncSetAttribute(flash16_kernel, cudaFuncAttributeMaxDynamicSharedMemorySize, FLASH16_SMEM);
    const int SM128 = (3 * 128 * HRS + 3 * 128 * HRS) * 2;
    const int SM64  = (3 * 128 * HRS + 3 * 64 * HRS) * 2;
    cudaFuncSetAttribute(h16gemm_k<false, 2, false, 128>, cudaFuncAttributeMaxDynamicSharedMemorySize, SM128);
    cudaFuncSetAttribute(h16gemm_k<true,  2, false, 128>, cudaFuncAttributeMaxDynamicSharedMemorySize, SM128);
    cudaFuncSetAttribute(h16gemm_k<false, 0, false, 64>,  cudaFuncAttributeMaxDynamicSharedMemorySize, SM64);
    cudaFuncSetAttribute(h16gemm_k<false, 0, true,  64>,  cudaFuncAttributeMaxDynamicSharedMemorySize, SM64);

    const long long NH  = (long long)NN * HD;
    const long long NH4 = (long long)NN * HD4;
    const long long NH2 = (long long)NN * 2 * HD;

    cudaStream_t sB, sP;
    cudaStreamCreateWithFlags(&sB, cudaStreamNonBlocking);
    cudaStreamCreateWithFlags(&sP, cudaStreamNonBlocking);
    cudaEvent_t evFork, evPrep, evEnd;
    cudaEventCreateWithFlags(&evFork, cudaEventDisableTiming);
    cudaEventCreateWithFlags(&evPrep, cudaEventDisableTiming);
    cudaEventCreateWithFlags(&evEnd, cudaEventDisableTiming);

    cudaEventRecord(evFork, 0);
    cudaStreamWaitEvent(sP, evFork, 0);
    {
        int total = 3 * 1536 * 384 + 3 * 1536 + 3 * 384 * 384 + 3 * 768 * 384 + 3 * 768 * 384;
        prep16_kernel<<<(total + 255) / 256, 256, 0, sP>>>(gcn_W, Wq, Wk, Wv, gcn_b, bq, bk, bv,
                                                           Wo, W1, W2, wpack16p, bpackp, wr16p);
    }
    cudaEventRecord(evPrep, sP);

    feats_kernel<<<(NB * NN * CIN + 255) / 256, 256>>>(x, featsp);
    cudaEventRecord(evFork, 0);
    cudaStreamWaitEvent(sB, evFork, 0);

    auto run_half = [&](int hb, cudaStream_t st) {
        long long off   = (long long)hb * HB * NH;
        long long off4  = (long long)hb * HB * NH4;
        long long off2  = (long long)hb * HB * NH2;
        long long offS  = (long long)hb * HB * NN * NN;
        long long offK  = (long long)hb * HB * NN * KNN;
        long long offF  = (long long)hb * HB * NN * CIN;

        gemm_f32(featsp + offF, W_enc, b_enc, nullptr, h0p + off,
                 NN, HD, CIN, CIN, HD, HD,
                 (long long)NN * CIN, 0, 0, 0, NH, 0, 1, HB, 1.f, false, false, st);
        norm_kernel<<<HB * NN, 128, 0, st>>>(h0p + off, nhp + off, h16p + off);

        sim_gemm_k<<<dim3(36, 1, HB), 256, 0, st>>>(nhp + off, simp + offS);
        topk_warp_kernel<<<HB * NN / 8, 256, 0, st>>>(simp + offS, knnp + offK);

        cudaStreamWaitEvent(st, evPrep, 0);

        const __half* hin = h16p + off;
        for (int l = 0; l < NL; l++) {
            const float* scl = lnsc + (l * 3) * HD;
            const float* bil = lnbi + (l * 3) * HD;

            h16gemm_k<false, 2, false, 128><<<dim3(12, 8, HB), 256, SM128, st>>>(
                hin, wpack16p + (long long)l * 1536 * 384, bpackp + l * 1536, nullptr,
                qkv16p + off4, HD, HD, HD, HD4, NH, NH4);

            gcn_agg_ln<<<HB * NN, 128, 0, st>>>(hin, qkv16p + off4, HD4, knnp + offK,
                                                scl, bil, hlocp + off);
            flash16_kernel<<<dim3(NN / 128, HB * NHE), 256, FLASH16_SMEM, st>>>(
                qkv16p + off4, ao16p + off);
            h16gemm_k<false, 0, false, 64><<<dim3(6, 8, HB), 256, SM64, st>>>(
                ao16p + off, wr16p + WR16_WO + (long long)l * 384 * 384, bo + l * HD, nullptr,
                op + off, HD, HD, 384, HD, NH, NH);
            add_ln_h<true><<<HB * NN, 128, 0, st>>>(hin, op + off, hlocp + off,
                                                    scl + HD, bil + HD, comb16p + off);

            h16gemm_k<true, 2, false, 128><<<dim3(6, 8, HB), 256, SM128, st>>>(
                comb16p + off, wr16p + WR16_W1 + (long long)l * 768 * 384, b1 + l * 2 * HD, nullptr,
                mlp116p + off2, HD, HD, 384, 2 * HD, NH, NH2);
            h16gemm_k<false, 0, true, 64><<<dim3(6, 8, HB), 256, SM64, st>>>(
                mlp116p + off2, wr16p + WR16_W2 + (long long)l * 384 * 768, b2 + l * HD,
                comb16p + off, ffp + off, 2 * HD, 2 * HD, 768, HD, NH2, NH);
            add_ln_h<false><<<HB * NN, 128, 0, st>>>(ffp + off, nullptr, nullptr,
                                                     scl + 2 * HD, bil + 2 * HD, hcur16p + off);
            hin = hcur16p + off;
        }

        pool_kernel<<<HB, HD, 0, st>>>(hin, poolp + hb * HB * HD);
        fin1_kernel<<<HB, HD, 0, st>>>(poolp + hb * HB * HD, lin1_W, lin1_b, zp + hb * HB * HD);
        fin2_kernel<<<HB, 128, 0, st>>>(zp + hb * HB * HD, lin2_W, lin2_b, outp + hb * HB * 128);
    };

    run_half(0, 0);
    run_half(1, sB);

    cudaEventRecord(evEnd, sB);
    cudaStreamWaitEvent(0, evEnd, 0);

    cudaEventDestroy(evFork);
    cudaEventDestroy(evPrep);
    cudaEventDestroy(evEnd);
    cudaStreamDestroy(sB);
    cudaStreamDestroy(sP);
}

// round 16
// speedup vs baseline: 1.3762x; 1.3762x over previous
#include <cuda_runtime.h>
#include <cuda_fp16.h>
#include <math.h>
#include <stdint.h>

// ---------------- problem constants ----------------
static const int NB   = 8;
static const int NN   = 1024;
static const int CIN  = 64;
static const int HD   = 384;
static const int NL   = 3;
static const int KNN  = 16;
static const int NHE  = 3;
static const int DHE  = 128;
static const int HD4  = 4 * HD;
static const int HB   = 4;     // batches per half-pipeline

// ---------------- device scratch (no allocs allowed) ----------------
__device__ float  g_feats [NB*NN*CIN];
__device__ float  g_h0    [NB*NN*HD];
__device__ float  g_nh    [NB*NN*HD];
__device__ float  g_sim   [NB*NN*NN];
__device__ int    g_knn   [NB*NN*KNN];
__device__ float  g_hloc  [NB*NN*HD];
__device__ float  g_o     [NB*NN*HD];
__device__ float  g_ff    [NB*NN*HD];
__device__ float  g_pool  [NB*HD];
__device__ float  g_z     [NB*HD];
__device__ float  g_bpack [3*1536];
// fp16 buffers
__device__ __half g_h16    [NB*NN*HD];
__device__ __half g_hcur16 [NB*NN*HD];
__device__ __half g_qkv16  [NB*NN*4*HD];   // packed [gcn | q | k | v] fp16
__device__ __half g_ao16   [NB*NN*HD];
__device__ __half g_comb16 [NB*NN*HD];
__device__ __half g_mlp116 [NB*NN*2*HD];
// fp16 weights, transposed to [N][K]
__device__ __half g_wpack16 [3*1536*384];
__device__ __half g_wr16    [2211840];
static const long long WR16_WO = 0;
static const long long WR16_W1 = 442368;
static const long long WR16_W2 = 1327104;

// ================= fp32 SIMT GEMM (exact: encoder) =========================
#define BM 128
#define BN 128
#define BKK 8
#define SPAD 132

template<bool TRANSB, bool RELU>
__global__ void __launch_bounds__(256, 2)
gemm_k(const float* __restrict__ A, const float* __restrict__ B,
       const float* __restrict__ bias, const float* __restrict__ Res,
       float* __restrict__ C,
       int M, int Nn, int K, int lda, int ldb, int ldc,
       long long sA, long long sAi, long long sB, long long sBi,
       long long sC, long long sCi, int zi, float alpha)
{
    int bz = blockIdx.z;
    int zo = bz / zi, zin = bz % zi;
    A += zo * sA + zin * sAi;
    B += zo * sB + zin * sBi;
    C += zo * sC + zin * sCi;
    if (Res) Res += zo * sC + zin * sCi;

    int m0 = blockIdx.y * BM;
    int n0 = blockIdx.x * BN;

    __shared__ float As[2][BKK][SPAD];
    __shared__ float Bs[2][BKK][SPAD];

    int tid = threadIdx.x;
    int tx = tid & 15;
    int ty = tid >> 4;

    int a_m = tid >> 1;
    int a_k = (tid & 1) * 4;
    const float* Aload = A + (long long)(m0 + a_m) * lda + a_k;

    const float* Bload;
    int b_k = 0, b_n = 0;
    if (TRANSB) {
        Bload = B + (long long)(n0 + a_m) * ldb + a_k;
    } else {
        b_k = tid >> 5;
        b_n = (tid & 31) * 4;
        Bload = B + (long long)b_k * ldb + n0 + b_n;
    }

    float4 av = *(const float4*)Aload;
    float4 bv = *(const float4*)Bload;

    As[0][a_k + 0][a_m] = av.x;
    As[0][a_k + 1][a_m] = av.y;
    As[0][a_k + 2][a_m] = av.z;
    As[0][a_k + 3][a_m] = av.w;
    if (TRANSB) {
        Bs[0][a_k + 0][a_m] = bv.x;
        Bs[0][a_k + 1][a_m] = bv.y;
        Bs[0][a_k + 2][a_m] = bv.z;
        Bs[0][a_k + 3][a_m] = bv.w;
    } else {
        *(float4*)&Bs[0][b_k][b_n] = bv;
    }
    __syncthreads();

    float acc[8][8];
    #pragma unroll
    for (int i = 0; i < 8; i++)
        #pragma unroll
        for (int j = 0; j < 8; j++) acc[i][j] = 0.f;

    int cur = 0;
    for (int k0 = 0; ; ) {
        int k1 = k0 + BKK;
        bool more = (k1 < K);
        if (more) {
            av = *(const float4*)(Aload + k1);
            if (TRANSB) bv = *(const float4*)(Bload + k1);
            else        bv = *(const float4*)(Bload + (long long)k1 * ldb);
        }

        #pragma unroll
        for (int kk = 0; kk < BKK; kk++) {
            float4 a0 = *(const float4*)&As[cur][kk][ty * 4];
            float4 a1 = *(const float4*)&As[cur][kk][64 + ty * 4];
            float4 b0 = *(const float4*)&Bs[cur][kk][tx * 4];
            float4 b1 = *(const float4*)&Bs[cur][kk][64 + tx * 4];
            float a[8] = {a0.x, a0.y, a0.z, a0.w, a1.x, a1.y, a1.z, a1.w};
            float b[8] = {b0.x, b0.y, b0.z, b0.w, b1.x, b1.y, b1.z, b1.w};
            #pragma unroll
            for (int i = 0; i < 8; i++)
                #pragma unroll
                for (int j = 0; j < 8; j++)
                    acc[i][j] = fmaf(a[i], b[j], acc[i][j]);
        }
        if (!more) break;

        int nxt = cur ^ 1;
        As[nxt][a_k + 0][a_m] = av.x;
        As[nxt][a_k + 1][a_m] = av.y;
        As[nxt][a_k + 2][a_m] = av.z;
        As[nxt][a_k + 3][a_m] = av.w;
        if (TRANSB) {
            Bs[nxt][a_k + 0][a_m] = bv.x;
            Bs[nxt][a_k + 1][a_m] = bv.y;
            Bs[nxt][a_k + 2][a_m] = bv.z;
            Bs[nxt][a_k + 3][a_m] = bv.w;
        } else {
            *(float4*)&Bs[nxt][b_k][b_n] = bv;
        }
        __syncthreads();
        cur = nxt;
        k0 = k1;
    }

    #pragma unroll
    for (int ih = 0; ih < 2; ih++) {
        #pragma unroll
        for (int i = 0; i < 4; i++) {
            int m = m0 + ih * 64 + ty * 4 + i;
            #pragma unroll
            for (int jh = 0; jh < 2; jh++) {
                int n = n0 + jh * 64 + tx * 4;
                float4 r;
                r.x = acc[ih * 4 + i][jh * 4 + 0] * alpha;
                r.y = acc[ih * 4 + i][jh * 4 + 1] * alpha;
                r.z = acc[ih * 4 + i][jh * 4 + 2] * alpha;
                r.w = acc[ih * 4 + i][jh * 4 + 3] * alpha;
                if (bias) {
                    float4 bb = *(const float4*)(bias + n);
                    r.x += bb.x; r.y += bb.y; r.z += bb.z; r.w += bb.w;
                }
                if (Res) {
                    float4 rr = *(const float4*)(Res + (long long)m * ldc + n);
                    r.x += rr.x; r.y += rr.y; r.z += rr.z; r.w += rr.w;
                }
                if (RELU) {
                    r.x = fmaxf(r.x, 0.f); r.y = fmaxf(r.y, 0.f);
                    r.z = fmaxf(r.z, 0.f); r.w = fmaxf(r.w, 0.f);
                }
                *(float4*)(C + (long long)m * ldc + n) = r;
            }
        }
    }
}

// ================= symmetric cosine-sim GEMM (fp32 exact) ==================
__global__ void __launch_bounds__(256, 2)
sim_gemm_k(const float* __restrict__ nh, float* __restrict__ sim)
{
    int t = blockIdx.x;
    int bi = 0;
    while ((bi + 1) * (bi + 2) / 2 <= t) bi++;
    int bj = t - bi * (bi + 1) / 2;
    int z = blockIdx.z;

    const float* A = nh + (long long)z * NN * HD;
    float* C = sim + (long long)z * NN * NN;
    int m0 = bi * 128;
    int n0 = bj * 128;

    __shared__ float As[2][BKK][SPAD];
    __shared__ float Bs[2][BKK][SPAD];

    int tid = threadIdx.x;
    int tx = tid & 15;
    int ty = tid >> 4;

    int a_m = tid >> 1;
    int a_k = (tid & 1) * 4;
    const float* Aload = A + (long long)(m0 + a_m) * HD + a_k;
    const float* Bload = A + (long long)(n0 + a_m) * HD + a_k;

    float4 av = *(const float4*)Aload;
    float4 bv = *(const float4*)Bload;

    As[0][a_k + 0][a_m] = av.x;
    As[0][a_k + 1][a_m] = av.y;
    As[0][a_k + 2][a_m] = av.z;
    As[0][a_k + 3][a_m] = av.w;
    Bs[0][a_k + 0][a_m] = bv.x;
    Bs[0][a_k + 1][a_m] = bv.y;
    Bs[0][a_k + 2][a_m] = bv.z;
    Bs[0][a_k + 3][a_m] = bv.w;
    __syncthreads();

    float acc[8][8];
    #pragma unroll
    for (int i = 0; i < 8; i++)
        #pragma unroll
        for (int j = 0; j < 8; j++) acc[i][j] = 0.f;

    int cur = 0;
    for (int k0 = 0; ; ) {
        int k1 = k0 + BKK;
        bool more = (k1 < HD);
        if (more) {
            av = *(const float4*)(Aload + k1);
            bv = *(const float4*)(Bload + k1);
        }
        #pragma unroll
        for (int kk = 0; kk < BKK; kk++) {
            float4 a0 = *(const float4*)&As[cur][kk][ty * 4];
            float4 a1 = *(const float4*)&As[cur][kk][64 + ty * 4];
            float4 b0 = *(const float4*)&Bs[cur][kk][tx * 4];
            float4 b1 = *(const float4*)&Bs[cur][kk][64 + tx * 4];
            float a[8] = {a0.x, a0.y, a0.z, a0.w, a1.x, a1.y, a1.z, a1.w};
            float b[8] = {b0.x, b0.y, b0.z, b0.w, b1.x, b1.y, b1.z, b1.w};
            #pragma unroll
            for (int i = 0; i < 8; i++)
                #pragma unroll
                for (int j = 0; j < 8; j++)
                    acc[i][j] = fmaf(a[i], b[j], acc[i][j]);
        }
        if (!more) break;

        int nxt = cur ^ 1;
        As[nxt][a_k + 0][a_m] = av.x;
        As[nxt][a_k + 1][a_m] = av.y;
        As[nxt][a_k + 2][a_m] = av.z;
        As[nxt][a_k + 3][a_m] = av.w;
        Bs[nxt][a_k + 0][a_m] = bv.x;
        Bs[nxt][a_k + 1][a_m] = bv.y;
        Bs[nxt][a_k + 2][a_m] = bv.z;
        Bs[nxt][a_k + 3][a_m] = bv.w;
        __syncthreads();
        cur = nxt;
        k0 = k1;
    }

    bool mirror = (bi != bj);
    #pragma unroll
    for (int ih = 0; ih < 2; ih++) {
        #pragma unroll
        for (int i = 0; i < 4; i++) {
            int m = m0 + ih * 64 + ty * 4 + i;
            #pragma unroll
            for (int jh = 0; jh < 2; jh++) {
                int n = n0 + jh * 64 + tx * 4;
                float4 r;
                r.x = acc[ih * 4 + i][jh * 4 + 0];
                r.y = acc[ih * 4 + i][jh * 4 + 1];
                r.z = acc[ih * 4 + i][jh * 4 + 2];
                r.w = acc[ih * 4 + i][jh * 4 + 3];
                *(float4*)(C + (long long)m * NN + n) = r;
                if (mirror) {
                    C[(long long)(n + 0) * NN + m] = r.x;
                    C[(long long)(n + 1) * NN + m] = r.y;
                    C[(long long)(n + 2) * NN + m] = r.z;
                    C[(long long)(n + 3) * NN + m] = r.w;
                }
            }
        }
    }
}

// ================= async + mma helpers ====================================
__device__ __forceinline__ void cpa16(void* dst, const void* src)
{
    uint32_t s = (uint32_t)__cvta_generic_to_shared(dst);
    asm volatile("cp.async.cg.shared.global [%0], [%1], 16;" :: "r"(s), "l"(src));
}
template<int N> __device__ __forceinline__ void cpa_wait()
{
    asm volatile("cp.async.wait_group %0;" :: "n"(N));
}
__device__ __forceinline__ void cpa_commit()
{
    asm volatile("cp.async.commit_group;");
}
__device__ __forceinline__ void mma_f16(float* d, const uint32_t* a, uint32_t b0, uint32_t b1)
{
    asm volatile(
        "mma.sync.aligned.m16n8k16.row.col.f32.f16.f16.f32 "
        "{%0,%1,%2,%3}, {%4,%5,%6,%7}, {%8,%9}, {%0,%1,%2,%3};"
        : "+f"(d[0]), "+f"(d[1]), "+f"(d[2]), "+f"(d[3])
        : "r"(a[0]), "r"(a[1]), "r"(a[2]), "r"(a[3]), "r"(b0), "r"(b1));
}
__device__ __forceinline__ uint32_t pack_h2(__half lo, __half hi)
{
    return (uint32_t)__half_as_ushort(lo) | ((uint32_t)__half_as_ushort(hi) << 16);
}

// ================= fp16 tensor-core GEMM ===================================
#define HRS 40

template<bool RELU, int OUTMODE, bool HASRES, int NTILE>
__global__ void __launch_bounds__(256, 2)
h16gemm_k(const __half* __restrict__ A, const __half* __restrict__ B,
          const float* __restrict__ bias, const __half* __restrict__ Res,
          void* __restrict__ Cv,
          int K, int lda, int ldb, int ldc,
          long long sA, long long sC)
{
    constexpr int NT  = NTILE / 16;
    constexpr int ASZ = 128 * HRS;
    constexpr int BSZ = NTILE * HRS;

    extern __shared__ __align__(16) __half hsm[];
    __half* As = hsm;
    __half* Bs = hsm + 3 * ASZ;

    int z = blockIdx.z;
    A += (long long)z * sA;
    long long coff = (long long)z * sC;

    int m0 = blockIdx.y * 128;
    int n0 = blockIdx.x * NTILE;

    int tid = threadIdx.x;
    int lane = tid & 31, wid = tid >> 5;
    int wm = (wid & 3) * 32;
    int wn = (wid >> 2) * (NTILE / 2);
    int tig = lane & 3, grp = lane >> 2;

    int ar0 = tid >> 2,          as0 = (tid & 3) * 8;
    int ar1 = (tid + 256) >> 2,  as1 = ((tid + 256) & 3) * 8;
    const __half* Ag0 = A + (long long)(m0 + ar0) * lda + as0;
    const __half* Ag1 = A + (long long)(m0 + ar1) * lda + as1;
    int ao0 = ar0 * HRS + as0;
    int ao1 = ar1 * HRS + as1;

    int br0 = tid >> 2, bs0 = (tid & 3) * 8;
    const __half* Bg0 = B + (long long)(n0 + br0) * ldb + bs0;
    int bo0 = br0 * HRS + bs0;
    const __half* Bg1 = nullptr; int bo1 = 0;
    if (NTILE == 128) {
        int br1 = (tid + 256) >> 2, bs1 = ((tid + 256) & 3) * 8;
        Bg1 = B + (long long)(n0 + br1) * ldb + bs1;
        bo1 = br1 * HRS + bs1;
    }

    const int kIt = K >> 5;

    cpa16(&As[ao0], Ag0);
    cpa16(&As[ao1], Ag1);
    cpa16(&Bs[bo0], Bg0);
    if (NTILE == 128) cpa16(&Bs[bo1], Bg1);
    cpa_commit();
    cpa16(&As[ASZ + ao0], Ag0 + 32);
    cpa16(&As[ASZ + ao1], Ag1 + 32);
    cpa16(&Bs[BSZ + bo0], Bg0 + 32);
    if (NTILE == 128) cpa16(&Bs[BSZ + bo1], Bg1 + 32);
    cpa_commit();

    float acc[2][NT][4];
    #pragma unroll
    for (int mt = 0; mt < 2; mt++)
        #pragma unroll
        for (int nt = 0; nt < NT; nt++)
            #pragma unroll
            for (int r = 0; r < 4; r++) acc[mt][nt][r] = 0.f;

    int bufm = 0;
    for (int it = 0; it < kIt; it++) {
        if (it + 1 < kIt) cpa_wait<1>(); else cpa_wait<0>();
        __syncthreads();

        if (it + 2 < kIt) {
            int pb = bufm + 2; if (pb >= 3) pb -= 3;
            int kf = (it + 2) << 5;
            cpa16(&As[pb * ASZ + ao0], Ag0 + kf);
            cpa16(&As[pb * ASZ + ao1], Ag1 + kf);
            cpa16(&Bs[pb * BSZ + bo0], Bg0 + kf);
            if (NTILE == 128) cpa16(&Bs[pb * BSZ + bo1], Bg1 + kf);
            cpa_commit();
        }

        const __half* Ac = As + bufm * ASZ;
        const __half* Bc = Bs + bufm * BSZ;
        #pragma unroll
        for (int ksi = 0; ksi < 2; ksi++) {
            int kc = ksi * 16;
            uint32_t af[2][4], bf[NT][2];
            #pragma unroll
            for (int mt = 0; mt < 2; mt++) {
                int mA = wm + mt * 16 + grp;
                af[mt][0] = *(const uint32_t*)&Ac[mA * HRS + kc + 2 * tig];
                af[mt][1] = *(const uint32_t*)&Ac[(mA + 8) * HRS + kc + 2 * tig];
                af[mt][2] = *(const uint32_t*)&Ac[mA * HRS + kc + 2 * tig + 8];
                af[mt][3] = *(const uint32_t*)&Ac[(mA + 8) * HRS + kc + 2 * tig + 8];
            }
            #pragma unroll
            for (int nt = 0; nt < NT; nt++) {
                int nB = wn + nt * 8 + grp;
                bf[nt][0] = *(const uint32_t*)&Bc[nB * HRS + kc + 2 * tig];
                bf[nt][1] = *(const uint32_t*)&Bc[nB * HRS + kc + 2 * tig + 8];
            }
            #pragma unroll
            for (int mt = 0; mt < 2; mt++)
                #pragma unroll
                for (int nt = 0; nt < NT; nt++)
                    mma_f16(acc[mt][nt], af[mt], bf[nt][0], bf[nt][1]);
        }
        bufm++; if (bufm >= 3) bufm = 0;
    }

    #pragma unroll
    for (int mt = 0; mt < 2; mt++) {
        #pragma unroll
        for (int hf = 0; hf < 2; hf++) {
            int m = m0 + wm + mt * 16 + grp + hf * 8;
            #pragma unroll
            for (int nt = 0; nt < NT; nt++) {
                int n = n0 + wn + nt * 8 + 2 * tig;
                float rx = acc[mt][nt][hf * 2 + 0] + bias[n];
                float ry = acc[mt][nt][hf * 2 + 1] + bias[n + 1];
                if (HASRES) {
                    __half2 rr = *(const __half2*)&Res[coff + (long long)m * ldc + n];
                    float2 rf = __half22float2(rr);
                    rx += rf.x; ry += rf.y;
                }
                if (RELU) { rx = fmaxf(rx, 0.f); ry = fmaxf(ry, 0.f); }
                if (OUTMODE == 2) {
                    *(__half2*)((__half*)Cv + coff + (long long)m * ldc + n) =
                        __floats2half2_rn(rx, ry);
                } else {
                    float2 r2; r2.x = rx; r2.y = ry;
                    *(float2*)((float*)Cv + coff + (long long)m * ldc + n) = r2;
                }
            }
        }
    }
}

// ================= fp16 flash attention (m16n8k16, online softmax) =========
#define QH 136
#define KH 136
#define VH 136
#define PH 40
static const int FLASH16_SMEM = (128*QH + 2*32*KH + 2*32*VH + 128*PH) * 2;

__global__ void __launch_bounds__(256, 2)
flash16_kernel(const __half* __restrict__ qkv, __half* __restrict__ ao)
{
    extern __shared__ __align__(16) __half fsm[];
    __half* Qs = fsm;                    // 128*QH
    __half* Ks = Qs + 128 * QH;          // 2*32*KH
    __half* Vs = Ks + 2 * 32 * KH;       // 2*32*VH
    __half* Ps = Vs + 2 * 32 * VH;       // 128*PH

    int qt = blockIdx.x;
    int bh = blockIdx.y;
    int b = bh / NHE, h = bh - b * NHE;
    const __half* qbase = qkv + (long long)b * NN * HD4 + (long long)qt * 128 * HD4 + HD + h * DHE;
    const __half* kbase = qkv + (long long)b * NN * HD4 + 2 * HD + h * DHE;
    const __half* vbase = qkv + (long long)b * NN * HD4 + 3 * HD + h * DHE;

    int tid = threadIdx.x;
    int lane = tid & 31, wid = tid >> 5;
    int tig = lane & 3, grp = lane >> 2;
    int wq = wid * 16;

    // Q: 128 rows x 16 chunks (8 halves) = 2048 chunks -> 8/thread
    #pragma unroll
    for (int c = 0; c < 8; c++) {
        int chunk = tid + c * 256;
        int row = chunk >> 4, col = (chunk & 15) * 8;
        cpa16(&Qs[row * QH + col], qbase + (long long)row * HD4 + col);
    }
    // K,V tile 0: 32 rows x 16 chunks = 512 -> 2/thread each
    #pragma unroll
    for (int c = 0; c < 2; c++) {
        int chunk = tid + c * 256;
        int row = chunk >> 4, col = (chunk & 15) * 8;
        cpa16(&Ks[row * KH + col], kbase + (long long)row * HD4 + col);
        cpa16(&Vs[row * VH + col], vbase + (long long)row * HD4 + col);
    }
    cpa_commit();

    float Oacc[16][4];
    #pragma unroll
    for (int nt = 0; nt < 16; nt++)
        #pragma unroll
        for (int j = 0; j < 4; j++) Oacc[nt][j] = 0.f;
    float m0r = -1e30f, m1r = -1e30f;
    float l0 = 0.f, l1 = 0.f;
    const float alpha = 0.08838834764831843f;

    int cur = 0;
    for (int it = 0; it < 32; it++) {
        bool more = (it + 1 < 32);
        if (more) {
            int nxt = cur ^ 1;
            const __half* kb = kbase + (long long)(it + 1) * 32 * HD4;
            const __half* vb = vbase + (long long)(it + 1) * 32 * HD4;
            #pragma unroll
            for (int c = 0; c < 2; c++) {
                int chunk = tid + c * 256;
                int row = chunk >> 4, col = (chunk & 15) * 8;
                cpa16(&Ks[nxt * 32 * KH + row * KH + col], kb + (long long)row * HD4 + col);
                cpa16(&Vs[nxt * 32 * VH + row * VH + col], vb + (long long)row * HD4 + col);
            }
            cpa_commit();
            cpa_wait<1>();
        } else {
            cpa_wait<0>();
        }
        __syncthreads();

        const __half* Kc = Ks + cur * 32 * KH;
        const __half* Vc = Vs + cur * 32 * VH;

        // S = Q @ K^T : k=128 -> 8 k16-steps, 4 n-frags (32 keys)
        float s[4][4];
        #pragma unroll
        for (int nt = 0; nt < 4; nt++)
            #pragma unroll
            for (int j = 0; j < 4; j++) s[nt][j] = 0.f;
        #pragma unroll
        for (int ks = 0; ks < 8; ks++) {
            int kc = ks * 16;
            uint32_t af[4];
            af[0] = *(const uint32_t*)&Qs[(wq + grp) * QH + kc + 2 * tig];
            af[1] = *(const uint32_t*)&Qs[(wq + grp + 8) * QH + kc + 2 * tig];
            af[2] = *(const uint32_t*)&Qs[(wq + grp) * QH + kc + 2 * tig + 8];
            af[3] = *(const uint32_t*)&Qs[(wq + grp + 8) * QH + kc + 2 * tig + 8];
            #pragma unroll
            for (int nt = 0; nt < 4; nt++) {
                int nB = nt * 8 + grp;
                uint32_t b0 = *(const uint32_t*)&Kc[nB * KH + kc + 2 * tig];
                uint32_t b1 = *(const uint32_t*)&Kc[nB * KH + kc + 2 * tig + 8];
                mma_f16(s[nt], af, b0, b1);
            }
        }

        // online softmax (fp32 exact)
        float t0 = -1e30f, t1 = -1e30f;
        #pragma unroll
        for (int nt = 0; nt < 4; nt++) {
            s[nt][0] *= alpha; s[nt][1] *= alpha;
            s[nt][2] *= alpha; s[nt][3] *= alpha;
            t0 = fmaxf(t0, fmaxf(s[nt][0], s[nt][1]));
            t1 = fmaxf(t1, fmaxf(s[nt][2], s[nt][3]));
        }
        t0 = fmaxf(t0, __shfl_xor_sync(0xffffffffu, t0, 1));
        t0 = fmaxf(t0, __shfl_xor_sync(0xffffffffu, t0, 2));
        t1 = fmaxf(t1, __shfl_xor_sync(0xffffffffu, t1, 1));
        t1 = fmaxf(t1, __shfl_xor_sync(0xffffffffu, t1, 2));
        float mn0 = fmaxf(m0r, t0), mn1 = fmaxf(m1r, t1);
        float f0 = __expf(m0r - mn0), f1 = __expf(m1r - mn1);
        float ps0 = 0.f, ps1 = 0.f;
        #pragma unroll
        for (int nt = 0; nt < 4; nt++) {
            float p0 = __expf(s[nt][0] - mn0);
            float p1 = __expf(s[nt][1] - mn0);
            float p2 = __expf(s[nt][2] - mn1);
            float p3 = __expf(s[nt][3] - mn1);
            ps0 += p0 + p1;
            ps1 += p2 + p3;
            *(__half2*)&Ps[(wq + grp) * PH + nt * 8 + 2 * tig] = __floats2half2_rn(p0, p1);
            *(__half2*)&Ps[(wq + grp + 8) * PH + nt * 8 + 2 * tig] = __floats2half2_rn(p2, p3);
        }
        ps0 += __shfl_xor_sync(0xffffffffu, ps0, 1);
        ps0 += __shfl_xor_sync(0xffffffffu, ps0, 2);
        ps1 += __shfl_xor_sync(0xffffffffu, ps1, 1);
        ps1 += __shfl_xor_sync(0xffffffffu, ps1, 2);
        l0 = l0 * f0 + ps0;
        l1 = l1 * f1 + ps1;
        m0r = mn0; m1r = mn1;
        #pragma unroll
        for (int nt = 0; nt < 16; nt++) {
            Oacc[nt][0] *= f0; Oacc[nt][1] *= f0;
            Oacc[nt][2] *= f1; Oacc[nt][3] *= f1;
        }
        __syncwarp();

        // O += P @ V : k=32 -> 2 k16-steps, 16 n-frags (dhe=128)
        #pragma unroll
        for (int ks = 0; ks < 2; ks++) {
            int kc = ks * 16;
            uint32_t af[4];
            af[0] = *(const uint32_t*)&Ps[(wq + grp) * PH + kc + 2 * tig];
            af[1] = *(const uint32_t*)&Ps[(wq + grp + 8) * PH + kc + 2 * tig];
            af[2] = *(const uint32_t*)&Ps[(wq + grp) * PH + kc + 2 * tig + 8];
            af[3] = *(const uint32_t*)&Ps[(wq + grp + 8) * PH + kc + 2 * tig + 8];
            int k0i = kc + 2 * tig;
            #pragma unroll
            for (int nt = 0; nt < 16; nt++) {
                int n = nt * 8 + grp;
                uint32_t b0 = pack_h2(Vc[k0i * VH + n], Vc[(k0i + 1) * VH + n]);
                uint32_t b1 = pack_h2(Vc[(k0i + 8) * VH + n], Vc[(k0i + 9) * VH + n]);
                mma_f16(Oacc[nt], af, b0, b1);
            }
        }
        if (!more) break;
        __syncthreads();
        cur ^= 1;
    }

    float inv0 = 1.f / l0, inv1 = 1.f / l1;
    int r0 = qt * 128 + wq + grp;
    __half* o0 = ao + ((long long)b * NN + r0) * HD + h * DHE;
    __half* o1 = o0 + 8 * HD;
    #pragma unroll
    for (int nt = 0; nt < 16; nt++) {
        int col = nt * 8 + 2 * tig;
        *(__half2*)(o0 + col) = __floats2half2_rn(Oacc[nt][0] * inv0, Oacc[nt][1] * inv0);
        *(__half2*)(o1 + col) = __floats2half2_rn(Oacc[nt][2] * inv1, Oacc[nt][3] * inv1);
    }
}

// ---------------- small kernels ----------------
__global__ void feats_kernel(const float* __restrict__ x, float* __restrict__ feats)
{
    long long i = (long long)blockIdx.x * blockDim.x + threadIdx.x;
    if (i >= (long long)NB * NN * CIN) return;
    int c = (int)(i & (CIN - 1));
    long long bn = i >> 6;
    int n = (int)(bn & (NN - 1));
    int b = (int)(bn >> 10);
    feats[i] = x[((long long)b * CIN + c) * NN + n];
}

__global__ void prep16_kernel(const float* __restrict__ gcn_W, const float* __restrict__ Wq,
                              const float* __restrict__ Wk, const float* __restrict__ Wv,
                              const float* __restrict__ gcn_b, const float* __restrict__ bq,
                              const float* __restrict__ bk, const float* __restrict__ bv,
                              const float* __restrict__ Wo, const float* __restrict__ W1,
                              const float* __restrict__ W2,
                              __half* __restrict__ wpack, float* __restrict__ bpack,
                              __half* __restrict__ wr)
{
    int i = blockIdx.x * blockDim.x + threadIdx.x;
    const int NWP = 3 * 1536 * 384;
    const int NBP = 3 * 1536;
    const int NWO = 3 * 384 * 384;
    const int NW1 = 3 * 768 * 384;
    if (i < NWP) {
        int l = i / (1536 * 384);
        int rem = i - l * (1536 * 384);
        int n = rem / 384;
        int k = rem - n * 384;
        int s2 = n / 384;
        int cc = n - s2 * 384;
        const float* src = (s2 == 0) ? gcn_W : (s2 == 1) ? Wq : (s2 == 2) ? Wk : Wv;
        wpack[i] = __float2half(src[((long long)l * 384 + k) * 384 + cc]);
        return;
    }
    int j = i - NWP;
    if (j < NBP) {
        int l = j / 1536;
        int c = j - l * 1536;
        int s2 = c / 384, cc = c - s2 * 384;
        const float* src = (s2 == 0) ? gcn_b : (s2 == 1) ? bq : (s2 == 2) ? bk : bv;
        bpack[j] = src[l * 384 + cc];
        return;
    }
    j -= NBP;
    if (j < NWO) {
        int l = j / (384 * 384);
        int rem = j - l * (384 * 384);
        int n = rem / 384, k = rem - n * 384;
        wr[WR16_WO + j] = __float2half(Wo[((long long)l * 384 + k) * 384 + n]);
        return;
    }
    j -= NWO;
    if (j < NW1) {
        int l = j / (768 * 384);
        int rem = j - l * (768 * 384);
        int n = rem / 384, k = rem - n * 384;
        wr[WR16_W1 + j] = __float2half(W1[((long long)l * 384 + k) * 768 + n]);
        return;
    }
    j -= NW1;
    if (j < NW1) {
        int l = j / (384 * 768);
        int rem = j - l * (384 * 768);
        int n = rem / 768, k = rem - n * 768;
        wr[WR16_W2 + j] = __float2half(W2[((long long)l * 768 + k) * 384 + n]);
        return;
    }
}

__device__ __forceinline__ void block_reduce2(float& s1, float& s2)
{
    __shared__ float b1[4], b2[4];
    #pragma unroll
    for (int o = 16; o > 0; o >>= 1) {
        s1 += __shfl_down_sync(0xffffffffu, s1, o);
        s2 += __shfl_down_sync(0xffffffffu, s2, o);
    }
    int w = threadIdx.x >> 5;
    if ((threadIdx.x & 31) == 0) { b1[w] = s1; b2[w] = s2; }
    __syncthreads();
    s1 = b1[0] + b1[1] + b1[2] + b1[3];
    s2 = b2[0] + b2[1] + b2[2] + b2[3];
}

__global__ void norm_kernel(const float* __restrict__ h0, float* __restrict__ nh,
                            __half* __restrict__ h16)
{
    long long bn = blockIdx.x;
    int t = threadIdx.x; // 128
    const float* r = h0 + bn * HD;
    float v0 = r[t], v1 = r[t + 128], v2 = r[t + 256];
    float ss = v0 * v0 + v1 * v1 + v2 * v2, dummy = 0.f;
    block_reduce2(ss, dummy);
    float rinv = rsqrtf(ss);
    float* o = nh + bn * HD;
    o[t] = v0 * rinv; o[t + 128] = v1 * rinv; o[t + 256] = v2 * rinv;
    __half* o2 = h16 + bn * HD;
    o2[t] = __float2half(v0);
    o2[t + 128] = __float2half(v1);
    o2[t + 256] = __float2half(v2);
}

__global__ void topk_warp_kernel(const float* __restrict__ sim, int* __restrict__ knn)
{
    int warp = blockIdx.x * (blockDim.x >> 5) + (threadIdx.x >> 5);
    int lane = threadIdx.x & 31;
    int n = warp & (NN - 1);
    const float* row = sim + (long long)warp * NN;
    float v[32];
    #pragma unroll
    for (int j = 0; j < 32; j++) {
        int m = j * 32 + lane;
        v[j] = (m == n) ? -3e38f : row[m];
    }
    unsigned taken = 0;
    int* o = knn + (long long)warp * KNN;
    for (int r = 0; r < KNN; r++) {
        float bv = -3e38f; int bj = 0;
        #pragma unroll
        for (int j = 0; j < 32; j++) {
            bool free_ = !((taken >> j) & 1u);
            if (free_ && v[j] > bv) { bv = v[j]; bj = j; }
        }
        int bidx = bj * 32 + lane;
        #pragma unroll
        for (int off = 16; off > 0; off >>= 1) {
            float ov = __shfl_xor_sync(0xffffffffu, bv, off);
            int   oi = __shfl_xor_sync(0xffffffffu, bidx, off);
            if (ov > bv || (ov == bv && oi < bidx)) { bv = ov; bidx = oi; }
        }
        if ((bidx & 31) == lane) taken |= 1u << (bidx >> 5);
        if (lane == 0) o[r] = bidx;
    }
}

// h_local = LN(hcur + agg/17); hcur fp16, xw fp16 (strided ldx halves)
__global__ void gcn_agg_ln(const __half* __restrict__ hcur, const __half* __restrict__ xw,
                           int ldx,
                           const int* __restrict__ knn,
                           const float* __restrict__ scale, const float* __restrict__ bias,
                           float* __restrict__ out)
{
    int bn = blockIdx.x;
    int b = bn >> 10;
    int t = threadIdx.x; // 128
    __shared__ int sidx[KNN];
    if (t < KNN) sidx[t] = knn[(long long)bn * KNN + t];
    __syncthreads();
    const __half* xr = xw + (long long)bn * ldx;
    float a0 = __half2float(xr[t]);
    float a1 = __half2float(xr[t + 128]);
    float a2 = __half2float(xr[t + 256]);
    #pragma unroll 4
    for (int j = 0; j < KNN; j++) {
        const __half* r = xw + ((long long)(b * NN) + sidx[j]) * ldx;
        a0 += __half2float(r[t]);
        a1 += __half2float(r[t + 128]);
        a2 += __half2float(r[t + 256]);
    }
    const __half* h = hcur + (long long)bn * HD;
    const float inv17 = 1.f / 17.f;
    float v0 = __half2float(h[t]) + a0 * inv17;
    float v1 = __half2float(h[t + 128]) + a1 * inv17;
    float v2 = __half2float(h[t + 256]) + a2 * inv17;
    float s1 = v0 + v1 + v2;
    float s2 = v0 * v0 + v1 * v1 + v2 * v2;
    block_reduce2(s1, s2);
    float mu = s1 * (1.f / HD);
    float var = s2 * (1.f / HD) - mu * mu;
    float rstd = rsqrtf(var + 1e-5f);
    float* o = out + (long long)bn * HD;
    o[t]       = (v0 - mu) * rstd * scale[t]       + bias[t];
    o[t + 128] = (v1 - mu) * rstd * scale[t + 128] + bias[t + 128];
    o[t + 256] = (v2 - mu) * rstd * scale[t + 256] + bias[t + 256];
}

template<bool AHALF>
__global__ void add_ln_h(const void* __restrict__ av, const float* __restrict__ b,
                         const float* __restrict__ plus,
                         const float* __restrict__ scale, const float* __restrict__ bias,
                         __half* __restrict__ out)
{
    long long bn = blockIdx.x;
    int t = threadIdx.x; // 128
    float v0, v1, v2;
    if (AHALF) {
        const __half* ar = (const __half*)av + bn * HD;
        v0 = __half2float(ar[t]);
        v1 = __half2float(ar[t + 128]);
        v2 = __half2float(ar[t + 256]);
    } else {
        const float* ar = (const float*)av + bn * HD;
        v0 = ar[t]; v1 = ar[t + 128]; v2 = ar[t + 256];
    }
    if (b) {
        const float* br = b + bn * HD;
        v0 += br[t]; v1 += br[t + 128]; v2 += br[t + 256];
    }
    float s1 = v0 + v1 + v2;
    float s2 = v0 * v0 + v1 * v1 + v2 * v2;
    block_reduce2(s1, s2);
    float mu = s1 * (1.f / HD);
    float var = s2 * (1.f / HD) - mu * mu;
    float rstd = rsqrtf(var + 1e-5f);
    float y0 = (v0 - mu) * rstd * scale[t]       + bias[t];
    float y1 = (v1 - mu) * rstd * scale[t + 128] + bias[t + 128];
    float y2 = (v2 - mu) * rstd * scale[t + 256] + bias[t + 256];
    if (plus) {
        const float* pr = plus + bn * HD;
        y0 += pr[t]; y1 += pr[t + 128]; y2 += pr[t + 256];
    }
    __half* o = out + bn * HD;
    o[t]       = __float2half(y0);
    o[t + 128] = __float2half(y1);
    o[t + 256] = __float2half(y2);
}

__global__ void pool_kernel(const __half* __restrict__ h, float* __restrict__ pooled)
{
    int b = blockIdx.x;
    int t = threadIdx.x; // 384
    float s = 0.f;
    const __half* base = h + (long long)b * NN * HD + t;
    for (int n = 0; n < NN; n++) s += __half2float(base[(long long)n * HD]);
    pooled[b * HD + t] = s * (1.f / NN);
}

__global__ void fin1_kernel(const float* __restrict__ pooled, const float* __restrict__ W,
                            const float* __restrict__ bias, float* __restrict__ z)
{
    int b = blockIdx.x;
    int j = threadIdx.x; // 384
    const float* p = pooled + b * HD;
    float s = bias[j];
    for (int k = 0; k < HD; k++) s = fmaf(p[k], W[k * HD + j], s);
    z[b * HD + j] = fmaxf(s, 0.f);
}

__global__ void fin2_kernel(const float* __restrict__ z, const float* __restrict__ W,
                            const float* __restrict__ bias, float* __restrict__ out)
{
    int b = blockIdx.x;
    int j = threadIdx.x; // 128
    const float* p = z + b * HD;
    float s = bias[j];
    for (int k = 0; k < HD; k++) s = fmaf(p[k], W[k * 128 + j], s);
    out[b * 128 + j] = s;
}

// ---------------- host helpers ----------------
static void gemm_f32(const float* A, const float* B, const float* bias, const float* Res, float* C,
                     int M, int Nn, int K, int lda, int ldb, int ldc,
                     long long sA, long long sAi, long long sB, long long sBi,
                     long long sC, long long sCi, int zi, int nz,
                     float alpha, bool transb, bool relu, cudaStream_t st = 0)
{
    dim3 grid(Nn / BN, M / BM, nz), block(256);
    if (transb) {
        if (relu) gemm_k<true, true ><<<grid, block, 0, st>>>(A, B, bias, Res, C, M, Nn, K, lda, ldb, ldc, sA, sAi, sB, sBi, sC, sCi, zi, alpha);
        else      gemm_k<true, false><<<grid, block, 0, st>>>(A, B, bias, Res, C, M, Nn, K, lda, ldb, ldc, sA, sAi, sB, sBi, sC, sCi, zi, alpha);
    } else {
        if (relu) gemm_k<false, true ><<<grid, block, 0, st>>>(A, B, bias, Res, C, M, Nn, K, lda, ldb, ldc, sA, sAi, sB, sBi, sC, sCi, zi, alpha);
        else      gemm_k<false, false><<<grid, block, 0, st>>>(A, B, bias, Res, C, M, Nn, K, lda, ldb, ldc, sA, sAi, sB, sBi, sC, sCi, zi, alpha);
    }
}

template<typename T> static T* sym_addr(const void* sym)
{
    void* p = nullptr;
    cudaGetSymbolAddress(&p, sym);
    return (T*)p;
}

extern "C" void kernel_launch(void* const* d_in, const int* in_sizes, int n_in,
                              void* d_out, int out_size)
{
    const float* x      = (const float*)d_in[0];
    const float* W_enc  = (const float*)d_in[1];
    const float* b_enc  = (const float*)d_in[2];
    const float* gcn_W  = (const float*)d_in[3];
    const float* gcn_b  = (const float*)d_in[4];
    const float* Wq     = (const float*)d_in[5];
    const float* bq     = (const float*)d_in[6];
    const float* Wk     = (const float*)d_in[7];
    const float* bk     = (const float*)d_in[8];
    const float* Wv     = (const float*)d_in[9];
    const float* bv     = (const float*)d_in[10];
    const float* Wo     = (const float*)d_in[11];
    const float* bo     = (const float*)d_in[12];
    const float* lnsc   = (const float*)d_in[13];
    const float* lnbi   = (const float*)d_in[14];
    const float* W1     = (const float*)d_in[15];
    const float* b1     = (const float*)d_in[16];
    const float* W2     = (const float*)d_in[17];
    const float* b2     = (const float*)d_in[18];
    const float* lin1_W = (const float*)d_in[19];
    const float* lin1_b = (const float*)d_in[20];
    const float* lin2_W = (const float*)d_in[21];
    const float* lin2_b = (const float*)d_in[22];
    float* outp = (float*)d_out;

    float*  featsp  = sym_addr<float>(g_feats);
    float*  h0p     = sym_addr<float>(g_h0);
    float*  nhp     = sym_addr<float>(g_nh);
    float*  simp    = sym_addr<float>(g_sim);
    int*    knnp    = sym_addr<int>(g_knn);
    float*  hlocp   = sym_addr<float>(g_hloc);
    float*  op      = sym_addr<float>(g_o);
    float*  ffp     = sym_addr<float>(g_ff);
    float*  poolp   = sym_addr<float>(g_pool);
    float*  zp      = sym_addr<float>(g_z);
    float*  bpackp  = sym_addr<float>(g_bpack);
    __half* h16p    = sym_addr<__half>(g_h16);
    __half* hcur16p = sym_addr<__half>(g_hcur16);
    __half* qkv16p  = sym_addr<__half>(g_qkv16);
    __half* ao16p   = sym_addr<__half>(g_ao16);
    __half* comb16p = sym_addr<__half>(g_comb16);
    __half* mlp116p = sym_addr<__half>(g_mlp116);
    __half* wpack16p= sym_addr<__half>(g_wpack16);
    __half* wr16p   = sym_addr<__half>(g_wr16);

    cudaFuncSetAttribute(flash16_kernel, cudaFuncAttributeMaxDynamicSharedMemorySize, FLASH16_SMEM);
    const int SM128 = (3 * 128 * HRS + 3 * 128 * HRS) * 2;
    const int SM64  = (3 * 128 * HRS + 3 * 64 * HRS) * 2;
    cudaFuncSetAttribute(h16gemm_k<false, 2, false, 128>, cudaFuncAttributeMaxDynamicSharedMemorySize, SM128);
    cudaFuncSetAttribute(h16gemm_k<true,  2, false, 128>, cudaFuncAttributeMaxDynamicSharedMemorySize, SM128);
    cudaFuncSetAttribute(h16gemm_k<false, 0, false, 64>,  cudaFuncAttributeMaxDynamicSharedMemorySize, SM64);
    cudaFuncSetAttribute(h16gemm_k<false, 0, true,  64>,  cudaFuncAttributeMaxDynamicSharedMemorySize, SM64);

    const long long NH  = (long long)NN * HD;
    const long long NH4 = (long long)NN * HD4;
    const long long NH2 = (long long)NN * 2 * HD;

    cudaStream_t sB, sP;
    cudaStreamCreateWithFlags(&sB, cudaStreamNonBlocking);
    cudaStreamCreateWithFlags(&sP, cudaStreamNonBlocking);
    cudaEvent_t evFork, evPrep, evEnd;
    cudaEventCreateWithFlags(&evFork, cudaEventDisableTiming);
    cudaEventCreateWithFlags(&evPrep, cudaEventDisableTiming);
    cudaEventCreateWithFlags(&evEnd, cudaEventDisableTiming);

    cudaEventRecord(evFork, 0);
    cudaStreamWaitEvent(sP, evFork, 0);
    {
        int total = 3 * 1536 * 384 + 3 * 1536 + 3 * 384 * 384 + 3 * 768 * 384 + 3 * 768 * 384;
        prep16_kernel<<<(total + 255) / 256, 256, 0, sP>>>(gcn_W, Wq, Wk, Wv, gcn_b, bq, bk, bv,
                                                           Wo, W1, W2, wpack16p, bpackp, wr16p);
    }
    cudaEventRecord(evPrep, sP);

    feats_kernel<<<(NB * NN * CIN + 255) / 256, 256>>>(x, featsp);
    cudaEventRecord(evFork, 0);
    cudaStreamWaitEvent(sB, evFork, 0);

    auto run_half = [&](int hb, cudaStream_t st) {
        long long off   = (long long)hb * HB * NH;
        long long off4  = (long long)hb * HB * NH4;
        long long off2  = (long long)hb * HB * NH2;
        long long offS  = (long long)hb * HB * NN * NN;
        long long offK  = (long long)hb * HB * NN * KNN;
        long long offF  = (long long)hb * HB * NN * CIN;

        gemm_f32(featsp + offF, W_enc, b_enc, nullptr, h0p + off,
                 NN, HD, CIN, CIN, HD, HD,
                 (long long)NN * CIN, 0, 0, 0, NH, 0, 1, HB, 1.f, false, false, st);
        norm_kernel<<<HB * NN, 128, 0, st>>>(h0p + off, nhp + off, h16p + off);

        sim_gemm_k<<<dim3(36, 1, HB), 256, 0, st>>>(nhp + off, simp + offS);
        topk_warp_kernel<<<HB * NN / 8, 256, 0, st>>>(simp + offS, knnp + offK);

        cudaStreamWaitEvent(st, evPrep, 0);

        const __half* hin = h16p + off;
        for (int l = 0; l < NL; l++) {
            const float* scl = lnsc + (l * 3) * HD;
            const float* bil = lnbi + (l * 3) * HD;

            // fused projection [gcn|q|k|v], fp16 in/out
            h16gemm_k<false, 2, false, 128><<<dim3(12, 8, HB), 256, SM128, st>>>(
                hin, wpack16p + (long long)l * 1536 * 384, bpackp + l * 1536, nullptr,
                qkv16p + off4, HD, HD, HD, HD4, NH, NH4);

            gcn_agg_ln<<<HB * NN, 128, 0, st>>>(hin, qkv16p + off4, HD4, knnp + offK,
                                                scl, bil, hlocp + off);
            flash16_kernel<<<dim3(NN / 128, HB * NHE), 256, FLASH16_SMEM, st>>>(
                qkv16p + off4, ao16p + off);
            h16gemm_k<false, 0, false, 64><<<dim3(6, 8, HB), 256, SM64, st>>>(
                ao16p + off, wr16p + WR16_WO + (long long)l * 384 * 384, bo + l * HD, nullptr,
                op + off, HD, HD, 384, HD, NH, NH);
            add_ln_h<true><<<HB * NN, 128, 0, st>>>(hin, op + off, hlocp + off,
                                                    scl + HD, bil + HD, comb16p + off);

            h16gemm_k<true, 2, false, 128><<<dim3(6, 8, HB), 256, SM128, st>>>(
                comb16p + off, wr16p + WR16_W1 + (long long)l * 768 * 384, b1 + l * 2 * HD, nullptr,
                mlp116p + off2, HD, HD, 384, 2 * HD, NH, NH2);
            h16gemm_k<false, 0, true, 64><<<dim3(6, 8, HB), 256, SM64, st>>>(
                mlp116p + off2, wr16p + WR16_W2 + (long long)l * 384 * 768, b2 + l * HD,
                comb16p + off, ffp + off, 2 * HD, 2 * HD, 768, HD, NH2, NH);
            add_ln_h<false><<<HB * NN, 128, 0, st>>>(ffp + off, nullptr, nullptr,
                                                     scl + 2 * HD, bil + 2 * HD, hcur16p + off);
            hin = hcur16p + off;
        }

        pool_kernel<<<HB, HD, 0, st>>>(hin, poolp + hb * HB * HD);
        fin1_kernel<<<HB, HD, 0, st>>>(poolp + hb * HB * HD, lin1_W, lin1_b, zp + hb * HB * HD);
        fin2_kernel<<<HB, 128, 0, st>>>(zp + hb * HB * HD, lin2_W, lin2_b, outp + hb * HB * 128);
    };

    run_half(0, 0);
    run_half(1, sB);

    cudaEventRecord(evEnd, sB);
    cudaStreamWaitEvent(0, evEnd, 0);

    cudaEventDestroy(evFork);
    cudaEventDestroy(evPrep);
    cudaEventDestroy(evEnd);
    cudaStreamDestroy(sB);
    cudaStreamDestroy(sP);
}